// round 4
// baseline (speedup 1.0000x reference)
#include <cuda_runtime.h>
#include <math.h>

#define NEG_F (-3.402823466e+38f)   // jnp.finfo(float32).min == -FLT_MAX
#define NBLOCKS 1184                // 148 SMs * 8 CTAs -> single wave
#define NTHREADS 256

// ---------------------------------------------------------------------------
// Persistent single-wave kernel. Each block owns rows {bid, bid+NBLOCKS, ...}.
//   Phase 1: fill every owned row with -FLT_MAX (coalesced float4 stores).
//   Phase 2: one __syncthreads, then all 256 threads cooperatively overwrite
//            the <=131 masked columns of each owned row with 0.0f. These hit
//            sectors still dirty in L2 from phase 1 -> merge, no extra DRAM.
// Masked columns per row:
//   - local window: dt,dh,dw in [-2,2]                      -> 125 candidates
//   - sparse pow2 {1,2,4} along exactly one axis (others 0) -> only +/-4 adds
//     new entries (1,2 lie inside the window)               ->   6 candidates
// ---------------------------------------------------------------------------
__global__ void __launch_bounds__(NTHREADS)
fused_mask_kernel(const int* __restrict__ tp, const int* __restrict__ hp,
                  const int* __restrict__ wp, float4* __restrict__ out4, int N) {
    const int n4  = N >> 2;             // float4s per row
    const int bid = blockIdx.x;
    const int tid = threadIdx.x;

    // ---- Phase 1: fill owned rows ----
    const float4 v = make_float4(NEG_F, NEG_F, NEG_F, NEG_F);
    for (int i = bid; i < N; i += NBLOCKS) {
        float4* row = out4 + (size_t)i * (size_t)n4;
        #pragma unroll 8
        for (int f = tid; f < n4; f += NTHREADS) row[f] = v;
    }

    __syncthreads();

    // ---- Phase 2: scatter zeros for owned rows, all threads cooperate ----
    const int t = *tp;
    const int h = *hp;
    const int w = *wp;

    // number of rows this block owns
    const int nrows = (N - bid + NBLOCKS - 1) / NBLOCKS;
    const int total = nrows * 131;      // (row_local, candidate) pairs

    for (int idx = tid; idx < total; idx += NTHREADS) {
        const int rl   = idx / 131;     // local row index
        const int cand = idx - rl * 131;
        const int i    = bid + rl * NBLOCKS;

        // decode row coordinate
        const int wi = i % w;
        const int ri = i / w;
        const int hi = ri % h;
        const int ti = ri / h;

        int dt, dh, dw;
        if (cand < 125) {
            dt = cand / 25 - 2;
            dh = (cand / 5) % 5 - 2;
            dw = cand % 5 - 2;
        } else {
            const int s    = cand - 125;       // 0..5
            const int axis = s >> 1;           // 0:t 1:h 2:w
            const int off  = (s & 1) ? 4 : -4;
            dt = (axis == 0) ? off : 0;
            dh = (axis == 1) ? off : 0;
            dw = (axis == 2) ? off : 0;
        }

        const int tj = ti + dt;
        const int hj = hi + dh;
        const int wj = wi + dw;
        if ((unsigned)tj < (unsigned)t &&
            (unsigned)hj < (unsigned)h &&
            (unsigned)wj < (unsigned)w) {
            const int j = (tj * h + hj) * w + wj;
            ((float*)(out4 + (size_t)i * (size_t)n4))[j] = 0.0f;
        }
    }
}

// ---------------------------------------------------------------------------
extern "C" void kernel_launch(void* const* d_in, const int* in_sizes, int n_in,
                              void* d_out, int out_size) {
    const int N = (int)(sqrt((double)out_size) + 0.5);   // out is N*N floats

    const int* tp = (const int*)d_in[0];
    const int* hp = (const int*)d_in[1];
    const int* wp = (const int*)d_in[2];

    fused_mask_kernel<<<NBLOCKS, NTHREADS>>>(tp, hp, wp, (float4*)d_out, N);
}

// round 6
// speedup vs baseline: 1.0894x; 1.0894x over previous
#include <cuda_runtime.h>
#include <cstdint>
#include <math.h>

#define NEG_F (-3.402823466e+38f)   // jnp.finfo(float32).min == -FLT_MAX
#define GRID_BLOCKS 444             // 148 SMs * 3 CTAs (64KB smem each)
#define NTHREADS 256

// ---------------------------------------------------------------------------
// TMA-store (cp.async.bulk S2G) mask generator.
// Two persistent SMEM row buffers (each N floats), initialized to -FLT_MAX
// once. Per owned row: wait for the bulk op that last read this buffer,
// restore its previously-zeroed cells to NEG, write this row's <=131 zeros,
// fence to the async proxy, and issue one bulk copy SMEM -> GMEM row.
// The global stores ride the bulk-async/LTS path, bypassing per-thread STG
// issue and the L1tex wavefront queue that bound the previous kernel.
// ---------------------------------------------------------------------------

// Write `val` at the valid masked columns of row i into buf. tid in [0,131).
__device__ __forceinline__ void write_candidates(
    float* __restrict__ buf, int i, int t, int h, int w, float val, int tid) {
    // decode row coordinate
    const int wi = i % w;
    const int ri = i / w;
    const int hi = ri % h;
    const int ti = ri / h;

    int dt, dh, dw;
    if (tid < 125) {
        dt = tid / 25 - 2;
        dh = (tid / 5) % 5 - 2;
        dw = tid % 5 - 2;
    } else {
        const int s    = tid - 125;        // 0..5
        const int axis = s >> 1;           // 0:t 1:h 2:w
        const int off  = (s & 1) ? 4 : -4;
        dt = (axis == 0) ? off : 0;
        dh = (axis == 1) ? off : 0;
        dw = (axis == 2) ? off : 0;
    }

    const int tj = ti + dt;
    const int hj = hi + dh;
    const int wj = wi + dw;
    if ((unsigned)tj < (unsigned)t &&
        (unsigned)hj < (unsigned)h &&
        (unsigned)wj < (unsigned)w) {
        buf[(tj * h + hj) * w + wj] = val;
    }
}

__device__ __forceinline__ unsigned int smem_u32(const void* p) {
    unsigned int a;
    asm("{ .reg .u64 tmp; cvta.to.shared.u64 tmp, %1; cvt.u32.u64 %0, tmp; }"
        : "=r"(a) : "l"(p));
    return a;
}

__global__ void __launch_bounds__(NTHREADS)
tma_mask_kernel(const int* __restrict__ tp, const int* __restrict__ hp,
                const int* __restrict__ wp, float* __restrict__ out, int N) {
    extern __shared__ float sm[];               // 2 * N floats
    const int bid = blockIdx.x;
    const int tid = threadIdx.x;

    const int t = *tp;
    const int h = *hp;
    const int w = *wp;

    // ---- one-time init: both buffers = -FLT_MAX ----
    {
        float4* s4 = (float4*)sm;
        const int tot4 = (2 * N) >> 2;
        const float4 v = make_float4(NEG_F, NEG_F, NEG_F, NEG_F);
        for (int f = tid; f < tot4; f += NTHREADS) s4[f] = v;
    }

    // ---- pipelined row loop ----
    int k = 0;
    for (int r = bid; r < N; r += GRID_BLOCKS, ++k) {
        float* buf = sm + (size_t)(k & 1) * (size_t)N;

        // free this buffer: wait until at most the most recent bulk group
        // still has pending smem reads (the one issued at k-1).
        if (tid == 0 && k >= 2) {
            asm volatile("cp.async.bulk.wait_group.read 1;" ::: "memory");
        }
        __syncthreads();

        // restore the zeros written for row r - 2*GRID_BLOCKS
        if (k >= 2 && tid < 131)
            write_candidates(buf, r - 2 * GRID_BLOCKS, t, h, w, NEG_F, tid);
        __syncthreads();   // restore/zero position sets may collide

        // write this row's zeros
        if (tid < 131)
            write_candidates(buf, r, t, h, w, 0.0f, tid);
        __syncthreads();

        // publish SMEM to the async proxy and issue the bulk store
        if (tid == 0) {
            asm volatile("fence.proxy.async.shared::cta;" ::: "memory");
            const float* grow = out + (size_t)r * (size_t)N;
            unsigned int saddr = smem_u32(buf);
            unsigned int bytes = (unsigned int)N * 4u;
            asm volatile(
                "cp.async.bulk.global.shared::cta.bulk_group [%0], [%1], %2;"
                :: "l"(grow), "r"(saddr), "r"(bytes) : "memory");
            asm volatile("cp.async.bulk.commit_group;" ::: "memory");
        }
    }

    // SMEM must stay alive until all bulk reads complete.
    if (tid == 0) {
        asm volatile("cp.async.bulk.wait_group.read 0;" ::: "memory");
    }
    __syncthreads();
}

// ---------------------------------------------------------------------------
extern "C" void kernel_launch(void* const* d_in, const int* in_sizes, int n_in,
                              void* d_out, int out_size) {
    const int N = (int)(sqrt((double)out_size) + 0.5);   // out is N*N floats

    const int* tp = (const int*)d_in[0];
    const int* hp = (const int*)d_in[1];
    const int* wp = (const int*)d_in[2];

    const size_t smem_bytes = (size_t)2 * (size_t)N * sizeof(float);
    // > 48KB dynamic smem requires opt-in (idempotent; not a stream op).
    cudaFuncSetAttribute(tma_mask_kernel,
                         cudaFuncAttributeMaxDynamicSharedMemorySize,
                         (int)smem_bytes);

    tma_mask_kernel<<<GRID_BLOCKS, NTHREADS, smem_bytes>>>(
        tp, hp, wp, (float*)d_out, N);
}

// round 7
// speedup vs baseline: 1.2197x; 1.1196x over previous
#include <cuda_runtime.h>
#include <cstdint>
#include <math.h>

#define NEG_F (-3.402823466e+38f)   // jnp.finfo(float32).min == -FLT_MAX
#define NTHREADS 256

// ---------------------------------------------------------------------------
// One block per row i of the N x N mask (N = t*h*w).
//   Phase 1: stream the whole row with -FLT_MAX using 256-bit stores
//            (st.global.v8.f32, sm_100a+) -> half the store instructions of
//            the float4 version, same coalescing.
//   Phase 2: after __syncthreads, threads 0..130 overwrite the <=131 masked
//            columns with 0.0f (lines still dirty in L2 -> merges, no extra
//            DRAM traffic).
// Masked columns per row:
//   - local window: dt,dh,dw in [-2,2]                      -> 125 candidates
//   - sparse pow2 {1,2,4} along exactly one axis (others 0) -> only +/-4 adds
//     new entries (1,2 lie inside the window)               ->   6 candidates
// ---------------------------------------------------------------------------
__global__ void __launch_bounds__(NTHREADS)
fused_mask_kernel(const int* __restrict__ tp, const int* __restrict__ hp,
                  const int* __restrict__ wp, float* __restrict__ out, int N) {
    const int i   = blockIdx.x;         // row index
    const int tid = threadIdx.x;
    float* row = out + (size_t)i * (size_t)N;

    // ---- Phase 1: fill row with -FLT_MAX via STG.256 ----
    const int n8 = N >> 3;              // float8 chunks per row
    const float v = NEG_F;
    #pragma unroll 4
    for (int f = tid; f < n8; f += NTHREADS) {
        float* p = row + ((size_t)f << 3);
        asm volatile(
            "st.global.v8.f32 [%0], {%1,%2,%3,%4,%5,%6,%7,%8};"
            :: "l"(p), "f"(v), "f"(v), "f"(v), "f"(v),
                       "f"(v), "f"(v), "f"(v), "f"(v)
            : "memory");
    }

    __syncthreads();

    // ---- Phase 2: overwrite masked columns with 0.0f ----
    if (tid < 131) {
        const int t = *tp;
        const int h = *hp;
        const int w = *wp;

        // decode row coordinate
        const int wi = i % w;
        const int ri = i / w;
        const int hi = ri % h;
        const int ti = ri / h;

        int dt, dh, dw;
        if (tid < 125) {
            dt = tid / 25 - 2;
            dh = (tid / 5) % 5 - 2;
            dw = tid % 5 - 2;
        } else {
            const int s    = tid - 125;        // 0..5
            const int axis = s >> 1;           // 0:t 1:h 2:w
            const int off  = (s & 1) ? 4 : -4;
            dt = (axis == 0) ? off : 0;
            dh = (axis == 1) ? off : 0;
            dw = (axis == 2) ? off : 0;
        }

        const int tj = ti + dt;
        const int hj = hi + dh;
        const int wj = wi + dw;
        if ((unsigned)tj < (unsigned)t &&
            (unsigned)hj < (unsigned)h &&
            (unsigned)wj < (unsigned)w) {
            const int j = (tj * h + hj) * w + wj;
            row[j] = 0.0f;
        }
    }
}

// ---------------------------------------------------------------------------
extern "C" void kernel_launch(void* const* d_in, const int* in_sizes, int n_in,
                              void* d_out, int out_size) {
    const int N = (int)(sqrt((double)out_size) + 0.5);   // out is N*N floats

    const int* tp = (const int*)d_in[0];
    const int* hp = (const int*)d_in[1];
    const int* wp = (const int*)d_in[2];

    fused_mask_kernel<<<N, NTHREADS>>>(tp, hp, wp, (float*)d_out, N);
}